// round 16
// baseline (speedup 1.0000x reference)
#include <cuda_runtime.h>
#include <cuda_fp16.h>
#include <cstdint>

// ---------------------------------------------------------------------------
// out[m, c] = sum_f sin(2*pi*f*t[m])*As[c,f] + cos(2*pi*f*t[m])*Ac[c,f]
// GEMM: M = 262144, N = 256, K = 256 (K = [sin | cos] halves).
// R16: R15 + A-FRAGMENT DEDUP. The 4 warps sharing wm need identical A
// fragments; previously each synthesized all of them (4x duplicated MUFU,
// ~58% of the cycle budget). Now warp (wm,wn) synthesizes only k-pairs
// {2wn, 2wn+1}, stores packed frags (consumer layout, lane-contiguous
// STS.128) to a 64KB SMEM staging area; after one __syncthreads the main
// loop fetches each pair's frags with 4 conflict-free LDS.128.
// MUFU per tile drops 4x; exchange adds ~2.5K crossbar cyc vs 6K saved.
// Everything else (512 thr, 4x4 warp grid, 32x64 tiles, B ping-pong,
// hoisted swizzle, paired sin/cos halves) as R15.
// ---------------------------------------------------------------------------

#define NT        512
#define MT        128                    // rows per CTA iteration
#define SA_OFF    131072                 // A-frag staging: 4 wm * 16KB
#define SF_OFF    196608
#define SMEM_TOTAL 197120                // W 128KB + staging 64KB + freqs

static __device__ __forceinline__ uint32_t smem_u32(const void* p) {
    uint32_t a;
    asm("{ .reg .u64 t; cvta.to.shared.u64 t, %1; cvt.u32.u64 %0, t; }"
        : "=r"(a) : "l"(p));
    return a;
}

// byte offset of (row, 16B-chunk) in a 512 B/row tile with XOR swizzle:
// chunk' = chunk ^ (row & 7). Conflict-free for ldmatrix and the fills.
static __device__ __forceinline__ uint32_t swz(uint32_t row, uint32_t chunk) {
    return row * 512u + ((chunk ^ (row & 7u)) << 4);
}

#define LDSM_X4(r, addr) \
    asm volatile("ldmatrix.sync.aligned.m8n8.x4.shared.b16 {%0,%1,%2,%3}, [%4];" \
        : "=r"((r)[0]), "=r"((r)[1]), "=r"((r)[2]), "=r"((r)[3]) : "r"(addr))

#define LDS128(r, addr) \
    asm volatile("ld.shared.v4.u32 {%0,%1,%2,%3}, [%4];" \
        : "=r"((r)[0]), "=r"((r)[1]), "=r"((r)[2]), "=r"((r)[3]) : "r"(addr))

#define STS128(addr, r) \
    asm volatile("st.shared.v4.u32 [%0], {%1,%2,%3,%4};" \
        :: "r"(addr), "r"((r)[0]), "r"((r)[1]), "r"((r)[2]), "r"((r)[3]) \
        : "memory")

#define MMA_16816(d, a, b0, b1) \
    asm volatile("mma.sync.aligned.m16n8k16.row.col.f32.f16.f16.f32 " \
        "{%0,%1,%2,%3}, {%4,%5,%6,%7}, {%8,%9}, {%0,%1,%2,%3};" \
        : "+f"((d)[0]), "+f"((d)[1]), "+f"((d)[2]), "+f"((d)[3]) \
        : "r"((a)[0]), "r"((a)[1]), "r"((a)[2]), "r"((a)[3]), \
          "r"(b0), "r"(b1))

static __device__ __forceinline__ uint32_t packh2(float x, float y) {
    __half2 h = __floats2half2_rn(x, y);
    return *reinterpret_cast<uint32_t*>(&h);
}

__global__ void __launch_bounds__(NT, 1)
fourier_mma_kernel(const float* __restrict__ t,
                   const float* __restrict__ freqs,
                   const float* __restrict__ As,
                   const float* __restrict__ Ac,
                   float* __restrict__ out,
                   int rows)
{
    extern __shared__ char smem[];
    char*  sW = smem;
    float* sF = (float*)(smem + SF_OFF);
    const uint32_t uW  = smem_u32(sW);
    const uint32_t uSA = uW + SA_OFF;

    const int tid  = threadIdx.x;
    const int lane = tid & 31;
    const int wid  = tid >> 5;

    // ---- one-time: freqs (x 2pi) + W fp32->fp16 into swizzled SMEM --------
    if (tid < 128) sF[tid] = freqs[tid] * 6.283185307179586f;
    for (int i = tid; i < 256 * 64; i += NT) {
        const int n  = i >> 6;
        const int j4 = i & 63;
        const int k0 = j4 << 2;
        const float* src = (k0 < 128) ? (As + n * 128 + k0)
                                      : (Ac + n * 128 + (k0 - 128));
        const float4 w = *reinterpret_cast<const float4*>(src);
        uint32_t byte = swz((uint32_t)n, (uint32_t)(j4 >> 1)) + ((uint32_t)(j4 & 1) << 3);
        uint2 v;
        v.x = packh2(w.x, w.y);
        v.y = packh2(w.z, w.w);
        *reinterpret_cast<uint2*>(sW + byte) = v;
    }

    // ---- warp grid 4 (M) x 4 (N); warp tile 32 x 64 -----------------------
    const int wm  = wid >> 2;
    const int wn  = wid & 3;
    const int gid = lane >> 2, tig = lane & 3;
    const int bRowOff = (lane & 7) + ((lane >> 4) << 3);
    const int bHi     = (lane >> 3) & 1;
    const uint32_t r7 = (uint32_t)(lane & 7);   // row&7, same for all B rows
    const float* fq = sF + tig * 2;        // per-pair: +16*kf, cols {0,1,8,9}

    // per-nt B base addresses (swizzle XOR applied separately per k-step)
    uint32_t baseB[4];
    #pragma unroll
    for (int nt = 0; nt < 4; nt++)
        baseB[nt] = uW + (uint32_t)(wn * 64 + nt * 16 + bRowOff) * 512u;

    // A-frag staging: addr(wm, ksp, i, lane) = uSA + wm*16KB + ((ksp*4+i)*32+lane)*16
    const uint32_t stgBase = uSA + (uint32_t)(wm * 16384 + lane * 16);

    const int numTiles = rows / MT;        // 2048
    const int stride   = gridDim.x;

    __syncthreads();                       // W + freqs visible

    for (int tile = blockIdx.x; tile < numTiles; tile += stride) {
        const int rbase = tile * MT + wm * 32 + gid;
        const float tv0 = t[rbase];
        const float tv1 = t[rbase + 8];
        const float tv2 = t[rbase + 16];
        const float tv3 = t[rbase + 24];

        // ==== PRODUCE: this warp's 2 k-pairs (dedup: 1/4 of the sincos) ====
        #pragma unroll
        for (int p = 0; p < 2; p++) {
            const int ksp = wn * 2 + p;
            const float Fa = fq[ksp * 16 + 0], Fb = fq[ksp * 16 + 1];
            const float Fc = fq[ksp * 16 + 8], Fd = fq[ksp * 16 + 9];
            uint32_t aS[2][4], aC[2][4];
            float s0, c0, s1, c1, s2, c2, s3, c3;
            __sincosf(tv0 * Fa, &s0, &c0); __sincosf(tv0 * Fb, &s1, &c1);
            __sincosf(tv0 * Fc, &s2, &c2); __sincosf(tv0 * Fd, &s3, &c3);
            aS[0][0] = packh2(s0, s1); aC[0][0] = packh2(c0, c1);
            aS[0][2] = packh2(s2, s3); aC[0][2] = packh2(c2, c3);
            __sincosf(tv1 * Fa, &s0, &c0); __sincosf(tv1 * Fb, &s1, &c1);
            __sincosf(tv1 * Fc, &s2, &c2); __sincosf(tv1 * Fd, &s3, &c3);
            aS[0][1] = packh2(s0, s1); aC[0][1] = packh2(c0, c1);
            aS[0][3] = packh2(s2, s3); aC[0][3] = packh2(c2, c3);
            __sincosf(tv2 * Fa, &s0, &c0); __sincosf(tv2 * Fb, &s1, &c1);
            __sincosf(tv2 * Fc, &s2, &c2); __sincosf(tv2 * Fd, &s3, &c3);
            aS[1][0] = packh2(s0, s1); aC[1][0] = packh2(c0, c1);
            aS[1][2] = packh2(s2, s3); aC[1][2] = packh2(c2, c3);
            __sincosf(tv3 * Fa, &s0, &c0); __sincosf(tv3 * Fb, &s1, &c1);
            __sincosf(tv3 * Fc, &s2, &c2); __sincosf(tv3 * Fd, &s3, &c3);
            aS[1][1] = packh2(s0, s1); aC[1][1] = packh2(c0, c1);
            aS[1][3] = packh2(s2, s3); aC[1][3] = packh2(c2, c3);

            const uint32_t sb = stgBase + (uint32_t)(ksp * 4) * 512u;
            STS128(sb,         aS[0]);
            STS128(sb +  512u, aS[1]);
            STS128(sb + 1024u, aC[0]);
            STS128(sb + 1536u, aC[1]);
        }
        __syncthreads();                   // staging visible to all wn

        float acc[2][8][4];
        #pragma unroll
        for (int mi = 0; mi < 2; mi++)
            #pragma unroll
            for (int ni = 0; ni < 8; ni++)
                #pragma unroll
                for (int q = 0; q < 4; q++) acc[mi][ni][q] = 0.0f;

        // ==== MAIN LOOP: consume staged A frags; B via ldmatrix ping-pong ==
        #pragma unroll 2
        for (int ksp = 0; ksp < 8; ksp++) {
            const uint32_t offS = (((uint32_t)(ksp * 2 + bHi)      ^ r7) << 4);
            const uint32_t offC = (((uint32_t)(ksp * 2 + 16 + bHi) ^ r7) << 4);

            // first sin-B fragment (longest latency)
            uint32_t bq[2][4];
            LDSM_X4(bq[0], baseB[0] + offS);

            // fetch this pair's A frags (conflict-free LDS.128)
            uint32_t aS[2][4], aC[2][4];
            const uint32_t sb = stgBase + (uint32_t)(ksp * 4) * 512u;
            LDS128(aS[0], sb);
            LDS128(aS[1], sb +  512u);
            LDS128(aC[0], sb + 1024u);
            LDS128(aC[1], sb + 1536u);

            // sin half: consume bq[nt&1], prefetch bq[(nt+1)&1]
            #pragma unroll
            for (int nt = 0; nt < 4; nt++) {
                if (nt < 3) LDSM_X4(bq[(nt + 1) & 1], baseB[nt + 1] + offS);
                else        LDSM_X4(bq[(nt + 1) & 1], baseB[0] + offC);
                const uint32_t* bb = bq[nt & 1];
                #pragma unroll
                for (int mi = 0; mi < 2; mi++) {
                    MMA_16816(acc[mi][nt * 2],     aS[mi], bb[0], bb[1]);
                    MMA_16816(acc[mi][nt * 2 + 1], aS[mi], bb[2], bb[3]);
                }
            }
            // cos half: same parity (cos tile 0 landed in bq[0])
            #pragma unroll
            for (int nt = 0; nt < 4; nt++) {
                if (nt < 3) LDSM_X4(bq[(nt + 1) & 1], baseB[nt + 1] + offC);
                const uint32_t* bb = bq[nt & 1];
                #pragma unroll
                for (int mi = 0; mi < 2; mi++) {
                    MMA_16816(acc[mi][nt * 2],     aC[mi], bb[0], bb[1]);
                    MMA_16816(acc[mi][nt * 2 + 1], aC[mi], bb[2], bb[3]);
                }
            }
        }
        __syncthreads();                   // all reads done before next fill

        // ---- epilogue: regs -> gmem (STG.64) ------------------------------
        #pragma unroll
        for (int mi = 0; mi < 2; mi++) {
            const size_t mrow = (size_t)(rbase + mi * 16);
            float* o0 = out + mrow * 256 + wn * 64 + tig * 2;
            #pragma unroll
            for (int ni = 0; ni < 8; ni++) {
                float2 v0, v1;
                v0.x = acc[mi][ni][0]; v0.y = acc[mi][ni][1];
                v1.x = acc[mi][ni][2]; v1.y = acc[mi][ni][3];
                *reinterpret_cast<float2*>(o0 + ni * 8)        = v0;  // row r
                *reinterpret_cast<float2*>(o0 + ni * 8 + 2048) = v1;  // row r+8
            }
        }
    }
}

extern "C" void kernel_launch(void* const* d_in, const int* in_sizes, int n_in,
                              void* d_out, int out_size)
{
    const float* t     = (const float*)d_in[0];
    const float* freqs = (const float*)d_in[1];
    const float* As    = (const float*)d_in[2];
    const float* Ac    = (const float*)d_in[3];
    float* out         = (float*)d_out;

    int sm_count = 148;
    cudaDeviceGetAttribute(&sm_count, cudaDevAttrMultiProcessorCount, 0);
    cudaFuncSetAttribute(fourier_mma_kernel,
                         cudaFuncAttributeMaxDynamicSharedMemorySize, SMEM_TOTAL);

    const int rows = in_sizes[0];          // B*L = 262144
    fourier_mma_kernel<<<sm_count, NT, SMEM_TOTAL>>>(t, freqs, As, Ac, out, rows);
}

// round 17
// speedup vs baseline: 1.3080x; 1.3080x over previous
#include <cuda_runtime.h>
#include <cuda_fp16.h>
#include <cstdint>

// ---------------------------------------------------------------------------
// out[m, c] = sum_f sin(2*pi*f*t[m])*As[c,f] + cos(2*pi*f*t[m])*Ac[c,f]
// GEMM: M = 262144, N = 256, K = 256 (K = [sin | cos] halves).
// R17: WARP-SPECIALIZED A DEDUP + CROSS-TILE DOUBLE BUFFER.
//   512 thr: warps 0-11 consumers (3M x 4N, MT=96, warp tile 32x64, acc=64
//   -> no spills), warps 12-15 producers (one per SMSP). Producers synth
//   A frags for tile t+stride into staging buf b^1 (consumer-lane layout,
//   STS.128) while consumers MMA tile t from buf b; ONE __syncthreads/tile.
//   MUFU per tile drops 4x (no wn duplication) and runs on different warps
//   than the MMA, so MUFU/tensor overlap across tiles instead of phasing
//   (R16's failure). Consumers: 4 LDS.128 per k-pair + B ldmatrix ping-pong.
// ---------------------------------------------------------------------------

#define NT        512
#define MT        96                     // rows per CTA iteration (3 x 32)
#define SA_OFF    131072                 // staging: 2 bufs x 48KB
#define SBUF      49152
#define SF_OFF    229376
#define SMEM_TOTAL 229888                // W 128K + 96K staging + freqs

static __device__ __forceinline__ uint32_t smem_u32(const void* p) {
    uint32_t a;
    asm("{ .reg .u64 t; cvta.to.shared.u64 t, %1; cvt.u32.u64 %0, t; }"
        : "=r"(a) : "l"(p));
    return a;
}

// byte offset of (row, 16B-chunk) in a 512 B/row tile with XOR swizzle.
static __device__ __forceinline__ uint32_t swz(uint32_t row, uint32_t chunk) {
    return row * 512u + ((chunk ^ (row & 7u)) << 4);
}

#define LDSM_X4(r, addr) \
    asm volatile("ldmatrix.sync.aligned.m8n8.x4.shared.b16 {%0,%1,%2,%3}, [%4];" \
        : "=r"((r)[0]), "=r"((r)[1]), "=r"((r)[2]), "=r"((r)[3]) : "r"(addr))

#define LDS128(r, addr) \
    asm volatile("ld.shared.v4.u32 {%0,%1,%2,%3}, [%4];" \
        : "=r"((r)[0]), "=r"((r)[1]), "=r"((r)[2]), "=r"((r)[3]) : "r"(addr))

#define STS128(addr, r) \
    asm volatile("st.shared.v4.u32 [%0], {%1,%2,%3,%4};" \
        :: "r"(addr), "r"((r)[0]), "r"((r)[1]), "r"((r)[2]), "r"((r)[3]) \
        : "memory")

#define MMA_16816(d, a, b0, b1) \
    asm volatile("mma.sync.aligned.m16n8k16.row.col.f32.f16.f16.f32 " \
        "{%0,%1,%2,%3}, {%4,%5,%6,%7}, {%8,%9}, {%0,%1,%2,%3};" \
        : "+f"((d)[0]), "+f"((d)[1]), "+f"((d)[2]), "+f"((d)[3]) \
        : "r"((a)[0]), "r"((a)[1]), "r"((a)[2]), "r"((a)[3]), \
          "r"(b0), "r"(b1))

static __device__ __forceinline__ uint32_t packh2(float x, float y) {
    __half2 h = __floats2half2_rn(x, y);
    return *reinterpret_cast<uint32_t*>(&h);
}

__global__ void __launch_bounds__(NT, 1)
fourier_mma_kernel(const float* __restrict__ t,
                   const float* __restrict__ freqs,
                   const float* __restrict__ As,
                   const float* __restrict__ Ac,
                   float* __restrict__ out,
                   int rows)
{
    extern __shared__ char smem[];
    char*  sW = smem;
    float* sF = (float*)(smem + SF_OFF);
    const uint32_t uW  = smem_u32(sW);
    const uint32_t uSA = uW + SA_OFF;

    const int tid  = threadIdx.x;
    const int lane = tid & 31;
    const int wid  = tid >> 5;
    const bool isProd = (wid >= 12);

    // ---- one-time: freqs (x 2pi) + W fp32->fp16 into swizzled SMEM --------
    if (tid < 128) sF[tid] = freqs[tid] * 6.283185307179586f;
    for (int i = tid; i < 256 * 64; i += NT) {
        const int n  = i >> 6;
        const int j4 = i & 63;
        const int k0 = j4 << 2;
        const float* src = (k0 < 128) ? (As + n * 128 + k0)
                                      : (Ac + n * 128 + (k0 - 128));
        const float4 w = *reinterpret_cast<const float4*>(src);
        uint32_t byte = swz((uint32_t)n, (uint32_t)(j4 >> 1)) + ((uint32_t)(j4 & 1) << 3);
        uint2 v;
        v.x = packh2(w.x, w.y);
        v.y = packh2(w.z, w.w);
        *reinterpret_cast<uint2*>(sW + byte) = v;
    }

    // ---- role constants ----------------------------------------------------
    const int gid = lane >> 2, tig = lane & 3;
    const float* fq = sF + tig * 2;        // per-pair: +16*ksp, cols {0,1,8,9}

    // consumers: warp grid 3 (M) x 4 (N), tile 32x64
    const int wm  = wid >> 2;              // 0..2 for consumers
    const int wn  = wid & 3;
    const int bRowOff = (lane & 7) + ((lane >> 4) << 3);
    const int bHi     = (lane >> 3) & 1;
    const uint32_t r7 = (uint32_t)(lane & 7);
    uint32_t baseB[4];
    #pragma unroll
    for (int nt = 0; nt < 4; nt++)
        baseB[nt] = uW + (uint32_t)(wn * 64 + nt * 16 + bRowOff) * 512u;

    // producers: warp 12+pw handles ksp pairs {2pw, 2pw+1} for all 3 wm
    const int pw = wid - 12;

    const int numTiles = (rows + MT - 1) / MT;   // 2731 (last tile 64 rows)
    const int stride   = gridDim.x;
    int tile = blockIdx.x;
    if (tile >= numTiles) return;

    __syncthreads();                       // W + freqs visible

    // ---- prologue: producers fill buf 0 for the first tile -----------------
    if (isProd) {
        #pragma unroll
        for (int wm2 = 0; wm2 < 3; wm2++) {
            const int rb = tile * MT + wm2 * 32 + gid;
            const float tv0 = t[min(rb,      rows - 1)];
            const float tv1 = t[min(rb + 8,  rows - 1)];
            const float tv2 = t[min(rb + 16, rows - 1)];
            const float tv3 = t[min(rb + 24, rows - 1)];
            #pragma unroll
            for (int p2 = 0; p2 < 2; p2++) {
                const int ksp = pw * 2 + p2;
                const float Fa = fq[ksp * 16 + 0], Fb = fq[ksp * 16 + 1];
                const float Fc = fq[ksp * 16 + 8], Fd = fq[ksp * 16 + 9];
                uint32_t aS[2][4], aC[2][4];
                float s0, c0, s1, c1, s2, c2, s3, c3;
                __sincosf(tv0 * Fa, &s0, &c0); __sincosf(tv0 * Fb, &s1, &c1);
                __sincosf(tv0 * Fc, &s2, &c2); __sincosf(tv0 * Fd, &s3, &c3);
                aS[0][0] = packh2(s0, s1); aC[0][0] = packh2(c0, c1);
                aS[0][2] = packh2(s2, s3); aC[0][2] = packh2(c2, c3);
                __sincosf(tv1 * Fa, &s0, &c0); __sincosf(tv1 * Fb, &s1, &c1);
                __sincosf(tv1 * Fc, &s2, &c2); __sincosf(tv1 * Fd, &s3, &c3);
                aS[0][1] = packh2(s0, s1); aC[0][1] = packh2(c0, c1);
                aS[0][3] = packh2(s2, s3); aC[0][3] = packh2(c2, c3);
                __sincosf(tv2 * Fa, &s0, &c0); __sincosf(tv2 * Fb, &s1, &c1);
                __sincosf(tv2 * Fc, &s2, &c2); __sincosf(tv2 * Fd, &s3, &c3);
                aS[1][0] = packh2(s0, s1); aC[1][0] = packh2(c0, c1);
                aS[1][2] = packh2(s2, s3); aC[1][2] = packh2(c2, c3);
                __sincosf(tv3 * Fa, &s0, &c0); __sincosf(tv3 * Fb, &s1, &c1);
                __sincosf(tv3 * Fc, &s2, &c2); __sincosf(tv3 * Fd, &s3, &c3);
                aS[1][1] = packh2(s0, s1); aC[1][1] = packh2(c0, c1);
                aS[1][3] = packh2(s2, s3); aC[1][3] = packh2(c2, c3);

                const uint32_t sb = uSA + (uint32_t)(wm2 * 16384 + ksp * 2048
                                                     + lane * 16);
                STS128(sb,         aS[0]);
                STS128(sb +  512u, aS[1]);
                STS128(sb + 1024u, aC[0]);
                STS128(sb + 1536u, aC[1]);
            }
        }
    }
    __syncthreads();

    int b = 0;
    for (; tile < numTiles; tile += stride, b ^= 1) {
        const int nextTile = tile + stride;

        if (!isProd) {
            // ================= CONSUMER =====================================
            const int rbase = tile * MT + wm * 32 + gid;
            const uint32_t sbuf = uSA + (uint32_t)(b * SBUF + wm * 16384
                                                   + lane * 16);
            float acc[2][8][4];
            #pragma unroll
            for (int mi = 0; mi < 2; mi++)
                #pragma unroll
                for (int ni = 0; ni < 8; ni++)
                    #pragma unroll
                    for (int q = 0; q < 4; q++) acc[mi][ni][q] = 0.0f;

            #pragma unroll 2
            for (int ksp = 0; ksp < 8; ksp++) {
                const uint32_t offS = (((uint32_t)(ksp * 2 + bHi)      ^ r7) << 4);
                const uint32_t offC = (((uint32_t)(ksp * 2 + 16 + bHi) ^ r7) << 4);

                uint32_t bq[2][4];
                LDSM_X4(bq[0], baseB[0] + offS);

                uint32_t aS[2][4], aC[2][4];
                const uint32_t sb = sbuf + (uint32_t)(ksp * 2048);
                LDS128(aS[0], sb);
                LDS128(aS[1], sb +  512u);
                LDS128(aC[0], sb + 1024u);
                LDS128(aC[1], sb + 1536u);

                #pragma unroll
                for (int nt = 0; nt < 4; nt++) {
                    if (nt < 3) LDSM_X4(bq[(nt + 1) & 1], baseB[nt + 1] + offS);
                    else        LDSM_X4(bq[(nt + 1) & 1], baseB[0] + offC);
                    const uint32_t* bb = bq[nt & 1];
                    #pragma unroll
                    for (int mi = 0; mi < 2; mi++) {
                        MMA_16816(acc[mi][nt * 2],     aS[mi], bb[0], bb[1]);
                        MMA_16816(acc[mi][nt * 2 + 1], aS[mi], bb[2], bb[3]);
                    }
                }
                #pragma unroll
                for (int nt = 0; nt < 4; nt++) {
                    if (nt < 3) LDSM_X4(bq[(nt + 1) & 1], baseB[nt + 1] + offC);
                    const uint32_t* bb = bq[nt & 1];
                    #pragma unroll
                    for (int mi = 0; mi < 2; mi++) {
                        MMA_16816(acc[mi][nt * 2],     aC[mi], bb[0], bb[1]);
                        MMA_16816(acc[mi][nt * 2 + 1], aC[mi], bb[2], bb[3]);
                    }
                }
            }

            // epilogue (guarded for the 64-row tail tile)
            #pragma unroll
            for (int mi = 0; mi < 2; mi++) {
                const int mrow = rbase + mi * 16;
                float* o0 = out + (size_t)mrow * 256 + wn * 64 + tig * 2;
                const bool in0 = mrow < rows;
                const bool in8 = mrow + 8 < rows;
                #pragma unroll
                for (int ni = 0; ni < 8; ni++) {
                    if (in0) {
                        float2 v0;
                        v0.x = acc[mi][ni][0]; v0.y = acc[mi][ni][1];
                        *reinterpret_cast<float2*>(o0 + ni * 8) = v0;
                    }
                    if (in8) {
                        float2 v1;
                        v1.x = acc[mi][ni][2]; v1.y = acc[mi][ni][3];
                        *reinterpret_cast<float2*>(o0 + ni * 8 + 2048) = v1;
                    }
                }
            }
        } else if (nextTile < numTiles) {
            // ================= PRODUCER: fill buf b^1 for nextTile ==========
            const uint32_t bufOff = (uint32_t)((b ^ 1) * SBUF);
            #pragma unroll
            for (int wm2 = 0; wm2 < 3; wm2++) {
                const int rb = nextTile * MT + wm2 * 32 + gid;
                const float tv0 = t[min(rb,      rows - 1)];
                const float tv1 = t[min(rb + 8,  rows - 1)];
                const float tv2 = t[min(rb + 16, rows - 1)];
                const float tv3 = t[min(rb + 24, rows - 1)];
                #pragma unroll
                for (int p2 = 0; p2 < 2; p2++) {
                    const int ksp = pw * 2 + p2;
                    const float Fa = fq[ksp * 16 + 0], Fb = fq[ksp * 16 + 1];
                    const float Fc = fq[ksp * 16 + 8], Fd = fq[ksp * 16 + 9];
                    uint32_t aS[2][4], aC[2][4];
                    float s0, c0, s1, c1, s2, c2, s3, c3;
                    __sincosf(tv0 * Fa, &s0, &c0); __sincosf(tv0 * Fb, &s1, &c1);
                    __sincosf(tv0 * Fc, &s2, &c2); __sincosf(tv0 * Fd, &s3, &c3);
                    aS[0][0] = packh2(s0, s1); aC[0][0] = packh2(c0, c1);
                    aS[0][2] = packh2(s2, s3); aC[0][2] = packh2(c2, c3);
                    __sincosf(tv1 * Fa, &s0, &c0); __sincosf(tv1 * Fb, &s1, &c1);
                    __sincosf(tv1 * Fc, &s2, &c2); __sincosf(tv1 * Fd, &s3, &c3);
                    aS[0][1] = packh2(s0, s1); aC[0][1] = packh2(c0, c1);
                    aS[0][3] = packh2(s2, s3); aC[0][3] = packh2(c2, c3);
                    __sincosf(tv2 * Fa, &s0, &c0); __sincosf(tv2 * Fb, &s1, &c1);
                    __sincosf(tv2 * Fc, &s2, &c2); __sincosf(tv2 * Fd, &s3, &c3);
                    aS[1][0] = packh2(s0, s1); aC[1][0] = packh2(c0, c1);
                    aS[1][2] = packh2(s2, s3); aC[1][2] = packh2(c2, c3);
                    __sincosf(tv3 * Fa, &s0, &c0); __sincosf(tv3 * Fb, &s1, &c1);
                    __sincosf(tv3 * Fc, &s2, &c2); __sincosf(tv3 * Fd, &s3, &c3);
                    aS[1][1] = packh2(s0, s1); aC[1][1] = packh2(c0, c1);
                    aS[1][3] = packh2(s2, s3); aC[1][3] = packh2(c2, c3);

                    const uint32_t sb = uSA + bufOff
                        + (uint32_t)(wm2 * 16384 + ksp * 2048 + lane * 16);
                    STS128(sb,         aS[0]);
                    STS128(sb +  512u, aS[1]);
                    STS128(sb + 1024u, aC[0]);
                    STS128(sb + 1536u, aC[1]);
                }
            }
        }

        // one barrier per tile: staging buf b free / buf b^1 published
        __syncthreads();
    }
}

extern "C" void kernel_launch(void* const* d_in, const int* in_sizes, int n_in,
                              void* d_out, int out_size)
{
    const float* t     = (const float*)d_in[0];
    const float* freqs = (const float*)d_in[1];
    const float* As    = (const float*)d_in[2];
    const float* Ac    = (const float*)d_in[3];
    float* out         = (float*)d_out;

    int sm_count = 148;
    cudaDeviceGetAttribute(&sm_count, cudaDevAttrMultiProcessorCount, 0);
    cudaFuncSetAttribute(fourier_mma_kernel,
                         cudaFuncAttributeMaxDynamicSharedMemorySize, SMEM_TOTAL);

    const int rows = in_sizes[0];          // B*L = 262144
    fourier_mma_kernel<<<sm_count, NT, SMEM_TOTAL>>>(t, freqs, As, Ac, out, rows);
}